// round 1
// baseline (speedup 1.0000x reference)
#include <cuda_runtime.h>
#include <math.h>

#define NN 100000
#define EE 3200000
#define F1 256
#define HID 128
#define NCLS 40

// ---------------- scratch (device globals; no allocation) ----------------
__device__ int g_deg[NN];
__device__ int g_rowstart[NN];
__device__ int g_cursor[NN];
__device__ int g_excl[NN];
__device__ int g_bsum[128];
__device__ int g_csrcol[EE];
__device__ float g_neigh1[(size_t)NN * F1];
__device__ float g_h1[(size_t)NN * HID];
__device__ float g_neigh2[(size_t)NN * HID];
__device__ float g_h2[(size_t)NN * HID];

// ---------------- CSR build ----------------
__global__ void k_zero() {
    int i = blockIdx.x * blockDim.x + threadIdx.x;
    if (i < NN) g_deg[i] = 0;
}

__global__ void k_hist(const int* __restrict__ rows) {
    int i = blockIdx.x * blockDim.x + threadIdx.x;
    if (i < EE) atomicAdd(&g_deg[rows[i]], 1);
}

__global__ void k_scan1() {
    __shared__ int s[1024];
    int gid = blockIdx.x * 1024 + threadIdx.x;
    int v = (gid < NN) ? g_deg[gid] : 0;
    s[threadIdx.x] = v;
    __syncthreads();
    #pragma unroll
    for (int off = 1; off < 1024; off <<= 1) {
        int t = (threadIdx.x >= off) ? s[threadIdx.x - off] : 0;
        __syncthreads();
        s[threadIdx.x] += t;
        __syncthreads();
    }
    if (gid < NN) g_excl[gid] = s[threadIdx.x] - v;
    if (threadIdx.x == 1023) g_bsum[blockIdx.x] = s[1023];
}

__global__ void k_scan2(int nb) {
    if (threadIdx.x == 0 && blockIdx.x == 0) {
        int run = 0;
        for (int i = 0; i < nb; i++) { int v = g_bsum[i]; g_bsum[i] = run; run += v; }
    }
}

__global__ void k_scan3() {
    int gid = blockIdx.x * blockDim.x + threadIdx.x;
    if (gid < NN) {
        int rs = g_excl[gid] + g_bsum[gid >> 10];
        g_rowstart[gid] = rs;
        g_cursor[gid] = rs;
    }
}

__global__ void k_scatter(const int* __restrict__ rows, const int* __restrict__ cols) {
    int i = blockIdx.x * blockDim.x + threadIdx.x;
    if (i < EE) {
        int r = rows[i];
        int p = atomicAdd(&g_cursor[r], 1);
        g_csrcol[p] = cols[i];
    }
}

// ---------------- SpMM (mean aggregate): one block per destination node ----------------
template <int LAYER>
__global__ void k_spmm(const float* __restrict__ xin) {
    constexpr int F = (LAYER == 1) ? 256 : 128;
    const float* feat = (LAYER == 1) ? xin : g_h1;
    float* out = (LAYER == 1) ? g_neigh1 : g_neigh2;

    __shared__ int scol[256];
    int n = blockIdx.x;
    int d = g_deg[n];
    int s = g_rowstart[n];
    int tid = threadIdx.x;
    float acc = 0.f;
    for (int base = 0; base < d; base += F) {
        int cnt = min(F, d - base);
        if (tid < cnt) scol[tid] = g_csrcol[s + base + tid];
        __syncthreads();
        #pragma unroll 4
        for (int j = 0; j < cnt; j++)
            acc += feat[(size_t)scol[j] * F + tid];
        __syncthreads();
    }
    out[(size_t)n * F + tid] = acc / ((float)d + 1.0f);
}

// ---------------- GEMM: h = relu([A0 | A1] @ W^T), 128x128 tile, 8x8 per thread ----------------
template <int LAYER>
__global__ void __launch_bounds__(256, 2) k_gemm(const float* __restrict__ xin,
                                                 const float* __restrict__ W) {
    constexpr int K0 = (LAYER == 1) ? 256 : 128;
    constexpr int K = 2 * K0;
    const float* A0 = (LAYER == 1) ? xin : g_h1;
    const float* A1 = (LAYER == 1) ? g_neigh1 : g_neigh2;
    float* C = (LAYER == 1) ? g_h1 : g_h2;

    __shared__ float As[16][128];
    __shared__ float Bs[16][128];

    int tid = threadIdx.x;
    int lrow = tid >> 1;       // 0..127
    int lseg = tid & 1;        // 0..1 (which 8-float k-subchunk)
    int tx = tid & 15, ty = tid >> 4;

    float acc[8][8];
    #pragma unroll
    for (int i = 0; i < 8; i++)
        #pragma unroll
        for (int j = 0; j < 8; j++) acc[i][j] = 0.f;

    int mbase = blockIdx.x * 128;
    int mload = min(mbase + lrow, NN - 1);

    for (int kc = 0; kc < K; kc += 16) {
        int ks = kc + lseg * 8;
        const float* src = (ks < K0) ? (A0 + (size_t)mload * K0 + ks)
                                     : (A1 + (size_t)mload * K0 + (ks - K0));
        float4 a0 = *(const float4*)(src);
        float4 a1 = *(const float4*)(src + 4);
        As[lseg * 8 + 0][lrow] = a0.x;
        As[lseg * 8 + 1][lrow] = a0.y;
        As[lseg * 8 + 2][lrow] = a0.z;
        As[lseg * 8 + 3][lrow] = a0.w;
        As[lseg * 8 + 4][lrow] = a1.x;
        As[lseg * 8 + 5][lrow] = a1.y;
        As[lseg * 8 + 6][lrow] = a1.z;
        As[lseg * 8 + 7][lrow] = a1.w;

        const float* wsrc = W + (size_t)lrow * K + ks;
        float4 b0 = *(const float4*)(wsrc);
        float4 b1 = *(const float4*)(wsrc + 4);
        Bs[lseg * 8 + 0][lrow] = b0.x;
        Bs[lseg * 8 + 1][lrow] = b0.y;
        Bs[lseg * 8 + 2][lrow] = b0.z;
        Bs[lseg * 8 + 3][lrow] = b0.w;
        Bs[lseg * 8 + 4][lrow] = b1.x;
        Bs[lseg * 8 + 5][lrow] = b1.y;
        Bs[lseg * 8 + 6][lrow] = b1.z;
        Bs[lseg * 8 + 7][lrow] = b1.w;

        __syncthreads();

        #pragma unroll
        for (int kk = 0; kk < 16; kk++) {
            float a[8], b[8];
            #pragma unroll
            for (int i = 0; i < 8; i++) a[i] = As[kk][ty * 8 + i];
            #pragma unroll
            for (int j = 0; j < 8; j++) b[j] = Bs[kk][tx * 8 + j];
            #pragma unroll
            for (int i = 0; i < 8; i++)
                #pragma unroll
                for (int j = 0; j < 8; j++) acc[i][j] += a[i] * b[j];
        }
        __syncthreads();
    }

    #pragma unroll
    for (int i = 0; i < 8; i++) {
        int m = mbase + ty * 8 + i;
        if (m < NN) {
            #pragma unroll
            for (int j = 0; j < 8; j++)
                C[(size_t)m * 128 + tx * 8 + j] = fmaxf(acc[i][j], 0.f);
        }
    }
}

// ---------------- MLP + log_softmax: one warp per node ----------------
__global__ void k_mlp(const float* __restrict__ Wm, const float* __restrict__ bias,
                      float* __restrict__ out) {
    __shared__ float sW[40 * 129];
    __shared__ float sb[40];
    __shared__ float sh[4][128];

    int tid = threadIdx.x;
    for (int idx = tid; idx < 40 * 128; idx += 128) {
        int c = idx >> 7, k = idx & 127;
        sW[c * 129 + k] = Wm[idx];
    }
    if (tid < 40) sb[tid] = bias[tid];
    __syncthreads();

    int warp = tid >> 5, lane = tid & 31;
    int n = blockIdx.x * 4 + warp;

    #pragma unroll
    for (int j = 0; j < 4; j++)
        sh[warp][lane + 32 * j] = g_h2[(size_t)n * 128 + lane + 32 * j];
    __syncwarp();

    float v1 = sb[lane];
    float v2 = (lane < 8) ? sb[lane + 32] : -1e30f;

    const float* swr1 = &sW[lane * 129];
    #pragma unroll 8
    for (int k = 0; k < 128; k++) v1 += sh[warp][k] * swr1[k];
    if (lane < 8) {
        const float* swr2 = &sW[(lane + 32) * 129];
        #pragma unroll 8
        for (int k = 0; k < 128; k++) v2 += sh[warp][k] * swr2[k];
    }

    float mx = fmaxf(v1, v2);
    #pragma unroll
    for (int o = 16; o; o >>= 1) mx = fmaxf(mx, __shfl_xor_sync(0xffffffffu, mx, o));
    float s = expf(v1 - mx) + ((lane < 8) ? expf(v2 - mx) : 0.f);
    #pragma unroll
    for (int o = 16; o; o >>= 1) s += __shfl_xor_sync(0xffffffffu, s, o);
    float lg = logf(s);

    out[(size_t)n * 40 + lane] = v1 - mx - lg;
    if (lane < 8) out[(size_t)n * 40 + lane + 32] = v2 - mx - lg;
}

// ---------------- launch ----------------
extern "C" void kernel_launch(void* const* d_in, const int* in_sizes, int n_in,
                              void* d_out, int out_size) {
    const float* x   = (const float*)d_in[0];
    const float* W1  = (const float*)d_in[1];
    const float* W2  = (const float*)d_in[2];
    const float* mW  = (const float*)d_in[3];
    const float* mb  = (const float*)d_in[4];
    const int*   er  = (const int*)d_in[5];
    const int*   ec  = (const int*)d_in[6];
    float* out = (float*)d_out;

    // CSR build (rebuilt every call — deterministic work)
    k_zero<<<(NN + 255) / 256, 256>>>();
    k_hist<<<(EE + 255) / 256, 256>>>(er);
    k_scan1<<<(NN + 1023) / 1024, 1024>>>();
    k_scan2<<<1, 32>>>((NN + 1023) / 1024);
    k_scan3<<<(NN + 255) / 256, 256>>>();
    k_scatter<<<(EE + 255) / 256, 256>>>(er, ec);

    // Layer 1
    k_spmm<1><<<NN, 256>>>(x);
    k_gemm<1><<<(NN + 127) / 128, 256>>>(x, W1);
    // Layer 2
    k_spmm<2><<<NN, 128>>>(x);
    k_gemm<2><<<(NN + 127) / 128, 256>>>(x, W2);
    // Head
    k_mlp<<<NN / 4, 128>>>(mW, mb, out);
}

// round 3
// speedup vs baseline: 1.6408x; 1.6408x over previous
#include <cuda_runtime.h>
#include <math.h>
#include <stdint.h>

#define NN 100000
#define EE 3200000
#define HID 128
#define NCLS 40
#define MTILES 782   // ceil(100000/128)

// ---------------- scratch (device globals; no allocation) ----------------
__device__ int g_deg[NN];
__device__ int g_rowstart[NN];
__device__ int g_cursor[NN];
__device__ int g_excl[NN];
__device__ int g_bsum[128];
__device__ int g_csrcol[EE];
__device__ float g_bufA[(size_t)NN * HID];   // Pa (self-projection)
__device__ float g_bufB[(size_t)NN * HID];   // Pb (neighbor-projection, pre-aggregation)
__device__ float g_h1[(size_t)NN * HID];
__device__ float g_h2[(size_t)NN * HID];

__device__ __forceinline__ float tf32r(float x) {
    float y; asm("cvt.rna.tf32.f32 %0, %1;" : "=f"(y) : "f"(x)); return y;
}

__device__ __forceinline__ void mma_tf32(float* c, const uint32_t* a, const uint32_t* b) {
    asm volatile(
        "mma.sync.aligned.m16n8k8.row.col.f32.tf32.tf32.f32 "
        "{%0,%1,%2,%3}, {%4,%5,%6,%7}, {%8,%9}, {%0,%1,%2,%3};"
        : "+f"(c[0]), "+f"(c[1]), "+f"(c[2]), "+f"(c[3])
        : "r"(a[0]), "r"(a[1]), "r"(a[2]), "r"(a[3]), "r"(b[0]), "r"(b[1]));
}

// ---------------- CSR build ----------------
__global__ void k_zero() {
    int i = blockIdx.x * blockDim.x + threadIdx.x;
    if (i < NN) g_deg[i] = 0;
}
__global__ void k_hist(const int* __restrict__ rows) {
    int i = blockIdx.x * blockDim.x + threadIdx.x;
    if (i < EE) atomicAdd(&g_deg[rows[i]], 1);
}
__global__ void k_scan1() {
    __shared__ int s[1024];
    int gid = blockIdx.x * 1024 + threadIdx.x;
    int v = (gid < NN) ? g_deg[gid] : 0;
    s[threadIdx.x] = v;
    __syncthreads();
    #pragma unroll
    for (int off = 1; off < 1024; off <<= 1) {
        int t = (threadIdx.x >= off) ? s[threadIdx.x - off] : 0;
        __syncthreads();
        s[threadIdx.x] += t;
        __syncthreads();
    }
    if (gid < NN) g_excl[gid] = s[threadIdx.x] - v;
    if (threadIdx.x == 1023) g_bsum[blockIdx.x] = s[1023];
}
__global__ void k_scan2(int nb) {
    if (threadIdx.x == 0 && blockIdx.x == 0) {
        int run = 0;
        for (int i = 0; i < nb; i++) { int v = g_bsum[i]; g_bsum[i] = run; run += v; }
    }
}
__global__ void k_scan3() {
    int gid = blockIdx.x * blockDim.x + threadIdx.x;
    if (gid < NN) {
        int rs = g_excl[gid] + g_bsum[gid >> 10];
        g_rowstart[gid] = rs;
        g_cursor[gid] = rs;
    }
}
__global__ void k_scatter(const int* __restrict__ rows, const int* __restrict__ cols) {
    int i = blockIdx.x * blockDim.x + threadIdx.x;
    if (i < EE) {
        int r = rows[i];
        int p = atomicAdd(&g_cursor[r], 1);
        g_csrcol[p] = cols[i];
    }
}

// ---------------- mma.sync tf32 GEMM: out = A[M,K] @ W[:, koff : koff+K]^T ----------------
// Block tile 128x128, 256 threads = 8 warps (4 m x 2 n), warp tile 32x64.
// K staged in chunks of 16 into SMEM (tf32-rounded), 2 k=8 mma steps per chunk.
template <int K, int LAYER>
__global__ void __launch_bounds__(256, 2) k_gemm_mma(const float* __restrict__ xin,
                                                     const float* __restrict__ W) {
    __shared__ float As[16][132];
    __shared__ float Bs[16][132];

    const float* A = (LAYER == 1) ? xin : g_h1;
    const int KW = 2 * K;
    const int koff = blockIdx.y * K;
    const int mbase = blockIdx.x * 128;

    const int tid = threadIdx.x;
    const int w = tid >> 5;
    const int lane = tid & 31;
    const int wm = w & 3;        // warp m index (0..3) -> rows wm*32
    const int wn = w >> 2;       // warp n index (0..1) -> cols wn*64
    const int gid = lane >> 2;   // 0..7
    const int tq = lane & 3;     // 0..3

    const int lrow = tid >> 1;   // 0..127 (load row)
    const int lhalf = tid & 1;   // which k-8 subchunk

    float c[2][8][4];
    #pragma unroll
    for (int i = 0; i < 2; i++)
        #pragma unroll
        for (int j = 0; j < 8; j++)
            #pragma unroll
            for (int q = 0; q < 4; q++) c[i][j][q] = 0.f;

    const int mload = min(mbase + lrow, NN - 1);

    for (int kc = 0; kc < K; kc += 16) {
        // stage A chunk (tf32-rounded), layout As[k][m]
        {
            const float* src = &A[(size_t)mload * K + kc + lhalf * 8];
            float4 v0 = *(const float4*)(src);
            float4 v1 = *(const float4*)(src + 4);
            int kb = lhalf * 8;
            As[kb + 0][lrow] = tf32r(v0.x);
            As[kb + 1][lrow] = tf32r(v0.y);
            As[kb + 2][lrow] = tf32r(v0.z);
            As[kb + 3][lrow] = tf32r(v0.w);
            As[kb + 4][lrow] = tf32r(v1.x);
            As[kb + 5][lrow] = tf32r(v1.y);
            As[kb + 6][lrow] = tf32r(v1.z);
            As[kb + 7][lrow] = tf32r(v1.w);

            const float* wsrc = &W[(size_t)lrow * KW + koff + kc + lhalf * 8];
            float4 b0 = *(const float4*)(wsrc);
            float4 b1 = *(const float4*)(wsrc + 4);
            Bs[kb + 0][lrow] = tf32r(b0.x);
            Bs[kb + 1][lrow] = tf32r(b0.y);
            Bs[kb + 2][lrow] = tf32r(b0.z);
            Bs[kb + 3][lrow] = tf32r(b0.w);
            Bs[kb + 4][lrow] = tf32r(b1.x);
            Bs[kb + 5][lrow] = tf32r(b1.y);
            Bs[kb + 6][lrow] = tf32r(b1.z);
            Bs[kb + 7][lrow] = tf32r(b1.w);
        }
        __syncthreads();

        #pragma unroll
        for (int kk = 0; kk < 16; kk += 8) {
            uint32_t a[2][4];
            #pragma unroll
            for (int mt = 0; mt < 2; mt++) {
                int rb = wm * 32 + mt * 16;
                a[mt][0] = __float_as_uint(As[kk + tq][rb + gid]);
                a[mt][1] = __float_as_uint(As[kk + tq][rb + gid + 8]);
                a[mt][2] = __float_as_uint(As[kk + tq + 4][rb + gid]);
                a[mt][3] = __float_as_uint(As[kk + tq + 4][rb + gid + 8]);
            }
            #pragma unroll
            for (int nt = 0; nt < 8; nt++) {
                int nb = wn * 64 + nt * 8;
                uint32_t b[2];
                b[0] = __float_as_uint(Bs[kk + tq][nb + gid]);
                b[1] = __float_as_uint(Bs[kk + tq + 4][nb + gid]);
                mma_tf32(c[0][nt], a[0], b);
                mma_tf32(c[1][nt], a[1], b);
            }
        }
        __syncthreads();
    }

    // epilogue: c{0,1} at (row, 2tq..2tq+1), c{2,3} at (row+8, ...)
    float* out = blockIdx.y ? g_bufB : g_bufA;
    #pragma unroll
    for (int mt = 0; mt < 2; mt++) {
        #pragma unroll
        for (int nt = 0; nt < 8; nt++) {
            int row = mbase + wm * 32 + mt * 16 + gid;
            int col = wn * 64 + nt * 8 + 2 * tq;
            if (row < NN) {
                float2 v0 = make_float2(c[mt][nt][0], c[mt][nt][1]);
                *(float2*)&out[(size_t)row * HID + col] = v0;
            }
            if (row + 8 < NN) {
                float2 v1 = make_float2(c[mt][nt][2], c[mt][nt][3]);
                *(float2*)&out[(size_t)(row + 8) * HID + col] = v1;
            }
        }
    }
}

// ---------------- SpMM fused: h = relu(Pa + agg(Pb)/(deg+1)) ----------------
template <int ROUND>
__global__ void k_spmm() {
    __shared__ int scol[128];
    const int n = blockIdx.x;
    const int tid = threadIdx.x;
    const int d = g_deg[n];
    const int s = g_rowstart[n];
    float acc = 0.f;
    for (int base = 0; base < d; base += 128) {
        int cnt = min(128, d - base);
        if (tid < cnt) scol[tid] = g_csrcol[s + base + tid];
        __syncthreads();
        #pragma unroll 4
        for (int j = 0; j < cnt; j++)
            acc += g_bufB[(size_t)scol[j] * HID + tid];
        __syncthreads();
    }
    float v = g_bufA[(size_t)n * HID + tid] + acc / ((float)d + 1.0f);
    v = fmaxf(v, 0.f);
    float* out = (ROUND == 1) ? g_h1 : g_h2;
    out[(size_t)n * HID + tid] = v;
}

// ---------------- MLP + log_softmax: one warp per node, 8 nodes/block ----------------
__global__ void k_mlp(const float* __restrict__ Wm, const float* __restrict__ bias,
                      float* __restrict__ out) {
    __shared__ float sW[NCLS * 129];
    __shared__ float sb[NCLS];
    __shared__ float sh[8][128];

    int tid = threadIdx.x;
    for (int idx = tid; idx < NCLS * 128; idx += 256) {
        int c = idx >> 7, k = idx & 127;
        sW[c * 129 + k] = Wm[idx];
    }
    if (tid < NCLS) sb[tid] = bias[tid];
    __syncthreads();

    int warp = tid >> 5, lane = tid & 31;
    int n = blockIdx.x * 8 + warp;

    #pragma unroll
    for (int j = 0; j < 4; j++)
        sh[warp][lane + 32 * j] = g_h2[(size_t)n * 128 + lane + 32 * j];
    __syncwarp();

    float v1 = sb[lane];
    float v2 = (lane < 8) ? sb[lane + 32] : -1e30f;

    const float* swr1 = &sW[lane * 129];
    #pragma unroll 8
    for (int k = 0; k < 128; k++) v1 += sh[warp][k] * swr1[k];
    if (lane < 8) {
        const float* swr2 = &sW[(lane + 32) * 129];
        #pragma unroll 8
        for (int k = 0; k < 128; k++) v2 += sh[warp][k] * swr2[k];
    }

    float mx = fmaxf(v1, v2);
    #pragma unroll
    for (int o = 16; o; o >>= 1) mx = fmaxf(mx, __shfl_xor_sync(0xffffffffu, mx, o));
    float s = expf(v1 - mx) + ((lane < 8) ? expf(v2 - mx) : 0.f);
    #pragma unroll
    for (int o = 16; o; o >>= 1) s += __shfl_xor_sync(0xffffffffu, s, o);
    float lg = logf(s);

    out[(size_t)n * NCLS + lane] = v1 - mx - lg;
    if (lane < 8) out[(size_t)n * NCLS + lane + 32] = v2 - mx - lg;
}

// ---------------- launch ----------------
extern "C" void kernel_launch(void* const* d_in, const int* in_sizes, int n_in,
                              void* d_out, int out_size) {
    const float* x  = (const float*)d_in[0];
    const float* W1 = (const float*)d_in[1];
    const float* W2 = (const float*)d_in[2];
    const float* mW = (const float*)d_in[3];
    const float* mb = (const float*)d_in[4];
    const int*   er = (const int*)d_in[5];
    const int*   ec = (const int*)d_in[6];
    float* out = (float*)d_out;

    // CSR build
    k_zero<<<(NN + 255) / 256, 256>>>();
    k_hist<<<(EE + 255) / 256, 256>>>(er);
    k_scan1<<<(NN + 1023) / 1024, 1024>>>();
    k_scan2<<<1, 32>>>((NN + 1023) / 1024);
    k_scan3<<<(NN + 255) / 256, 256>>>();
    k_scatter<<<(EE + 255) / 256, 256>>>(er, ec);

    // Layer 1: Pa = x@Wa^T, Pb = x@Wb^T, then h1 = relu(Pa + agg(Pb))
    k_gemm_mma<256, 1><<<dim3(MTILES, 2), 256>>>(x, W1);
    k_spmm<1><<<NN, 128>>>();
    // Layer 2
    k_gemm_mma<128, 2><<<dim3(MTILES, 2), 256>>>(x, W2);
    k_spmm<2><<<NN, 128>>>();
    // Head
    k_mlp<<<NN / 8, 256>>>(mW, mb, out);
}